// round 4
// baseline (speedup 1.0000x reference)
#include <cuda_runtime.h>
#include <cuda_bf16.h>
#include <cstdint>

// ESN reservoir: B=256, T=4096, D=8, U=64, leaky=1.0
// state_t = tanh(x_proj_t + state_{t-1} @ W_rec), W_rec ~64 nnz total.
//
// State in registers: lane L holds units g_unitOf[0][L] (reg n0) and
// g_unitOf[1][L] (reg n1). The unit->(lane,slot) assignment is chosen by a
// greedy balancer in the prep kernel so each column's sources split evenly
// across the two register slots -> per-(col,slot) cap of 4 -> 16 shuffles
// per step instead of 24. Overflow (cap exceeded) handled exactly via a
// warp-uniform SMEM fallback (normally empty).
// Each warp processes TWO batches (independent chains, ILP).

#define BATCH  256
#define TLEN   4096
#define DIN    8
#define UNITS  64
#define CAP    4
#define DEGCAP 12
#define CHUNK  64
#define NCHUNK (TLEN / CHUNK)
#define FULLMASK 0xffffffffu

__device__ int   g_unitOf[2][32];          // [slot][lane] -> unit id
__device__ int   g_lsrc[UNITS][2][CAP];    // [col][slot][k] -> source lane
__device__ float g_lval[UNITS][2][CAP];
__device__ int   g_nover;
__device__ int   g_ovdst[256];
__device__ int   g_ovsrc[256];
__device__ float g_ovval[256];

__global__ void esn_prep_kernel(const float* __restrict__ W) {
    __shared__ int   s_cols[UNITS][DEGCAP];
    __shared__ float s_vals[UNITS][DEGCAP];
    __shared__ int   s_deg[UNITS];
    __shared__ int   s_slot[UNITS], s_lane[UNITS];
    __shared__ int   s_ovn[UNITS];
    __shared__ int   s_ovsrc[UNITS][8];
    __shared__ float s_ovval[UNITS][8];

    const int tid = threadIdx.x;

    // Phase A (parallel): per-source (row) nonzero lists.
    if (tid < UNITS) {
        int d = 0;
        for (int c = 0; c < UNITS; ++c) {
            float v = W[tid * UNITS + c];
            if (v != 0.0f && d < DEGCAP) { s_cols[tid][d] = c; s_vals[tid][d] = v; ++d; }
        }
        s_deg[tid] = d;
    }
    __syncthreads();

    // Phase B (serial, deterministic): greedy slot assignment balancing each
    // column's source count across the two register slots.
    if (tid == 0) {
        int load[UNITS][2];
        for (int c = 0; c < UNITS; ++c) { load[c][0] = 0; load[c][1] = 0; }
        int cnt0 = 0, cnt1 = 0;
        for (int j = 0; j < UNITS; ++j) {
            int c0 = 0, c1 = 0;
            for (int k = 0; k < s_deg[j]; ++k) {
                int c = s_cols[j][k];
                if (load[c][0] > c0) c0 = load[c][0];
                if (load[c][1] > c1) c1 = load[c][1];
            }
            int s;
            if (cnt0 >= 32) s = 1;
            else if (cnt1 >= 32) s = 0;
            else if (c0 != c1) s = (c0 < c1) ? 0 : 1;
            else s = (cnt0 <= cnt1) ? 0 : 1;
            s_slot[j] = s;
            s_lane[j] = (s == 0) ? cnt0++ : cnt1++;
            for (int k = 0; k < s_deg[j]; ++k) load[s_cols[j][k]][s]++;
        }
    }
    __syncthreads();

    // Phase C (parallel): per-column shuffle lists + per-column overflow.
    if (tid < UNITS) {
        const int c = tid;
        int n0 = 0, n1 = 0, ovn = 0;
        for (int j = 0; j < UNITS; ++j) {
            float v = W[j * UNITS + c];
            if (v == 0.0f) continue;
            int s = s_slot[j];
            if (s == 0 && n0 < CAP)      { g_lsrc[c][0][n0] = s_lane[j]; g_lval[c][0][n0] = v; ++n0; }
            else if (s == 1 && n1 < CAP) { g_lsrc[c][1][n1] = s_lane[j]; g_lval[c][1][n1] = v; ++n1; }
            else if (ovn < 8)            { s_ovsrc[c][ovn] = j; s_ovval[c][ovn] = v; ++ovn; }
        }
        for (int k = n0; k < CAP; ++k) { g_lsrc[c][0][k] = 0; g_lval[c][0][k] = 0.0f; }
        for (int k = n1; k < CAP; ++k) { g_lsrc[c][1][k] = 0; g_lval[c][1][k] = 0.0f; }
        s_ovn[c] = ovn;
        // inverse map: unit tid lives at (slot, lane)
        g_unitOf[s_slot[tid]][s_lane[tid]] = tid;
    }
    __syncthreads();

    // Phase D (serial, deterministic): compact overflow entries.
    if (tid == 0) {
        int n = 0;
        for (int c = 0; c < UNITS; ++c)
            for (int k = 0; k < s_ovn[c]; ++k) {
                g_ovdst[n] = c; g_ovsrc[n] = s_ovsrc[c][k]; g_ovval[n] = s_ovval[c][k]; ++n;
            }
        g_nover = n;
    }
}

// tanh(x) = (e-1)*rcp(e+1), e = exp(2x). Chain ~44 cyc, rel err ~1e-6.
__device__ __forceinline__ float fast_tanh(float x) {
    float e;
    asm("ex2.approx.f32 %0, %1;" : "=f"(e) : "f"(x * 2.8853900817779268f));
    float r;
    asm("rcp.approx.f32 %0, %1;" : "=f"(r) : "f"(e + 1.0f));
    return (e - 1.0f) * r;
}

__device__ __forceinline__ void cp_async16(void* smem_dst, const void* gmem_src) {
    uint32_t s = (uint32_t)__cvta_generic_to_shared(smem_dst);
    asm volatile("cp.async.cg.shared.global [%0], [%1], 16;\n" :: "r"(s), "l"(gmem_src));
}
__device__ __forceinline__ void cp_async_commit() {
    asm volatile("cp.async.commit_group;\n");
}
__device__ __forceinline__ void cp_async_wait1() {
    asm volatile("cp.async.wait_group 1;\n");
}

__global__ void __launch_bounds__(32)
esn_main_kernel(const float* __restrict__ inputs,
                const float* __restrict__ W_in,
                const float* __restrict__ bias,
                float* __restrict__ out) {
    const int lane = threadIdx.x;
    const int bA = blockIdx.x * 2;
    const int bB = bA + 1;

    __shared__ float xinA[2][CHUNK * DIN];
    __shared__ float xinB[2][CHUNK * DIN];
    __shared__ float shA[UNITS];
    __shared__ float shB[UNITS];

    const int u0 = g_unitOf[0][lane];   // unit in reg slot 0
    const int u1 = g_unitOf[1][lane];   // unit in reg slot 1

    float win0[DIN], win1[DIN];
#pragma unroll
    for (int d = 0; d < DIN; ++d) {
        win0[d] = W_in[d * UNITS + u0];
        win1[d] = W_in[d * UNITS + u1];
    }
    const float b0 = bias[u0];
    const float b1 = bias[u1];

    // Shuffle lists for this lane's two columns (shared across both batches).
    int   s00[CAP], s01[CAP], s10[CAP], s11[CAP];
    float v00[CAP], v01[CAP], v10[CAP], v11[CAP];
#pragma unroll
    for (int k = 0; k < CAP; ++k) {
        s00[k] = g_lsrc[u0][0][k];  v00[k] = g_lval[u0][0][k];
        s01[k] = g_lsrc[u0][1][k];  v01[k] = g_lval[u0][1][k];
        s10[k] = g_lsrc[u1][0][k];  v10[k] = g_lval[u1][0][k];
        s11[k] = g_lsrc[u1][1][k];  v11[k] = g_lval[u1][1][k];
    }
    const int nover = g_nover;

    float nA0 = 0.0f, nA1 = 0.0f;   // batch A states (units u0, u1)
    float nB0 = 0.0f, nB1 = 0.0f;   // batch B states

    const float* inA = inputs + (size_t)bA * TLEN * DIN;
    const float* inB = inputs + (size_t)bB * TLEN * DIN;
    float* outA = out + (size_t)bA * TLEN * UNITS;
    float* outB = out + (size_t)bB * TLEN * UNITS;

    // Prefetch input chunks 0 and 1 for both batches.
#pragma unroll
    for (int c = 0; c < 2; ++c) {
#pragma unroll
        for (int i = 0; i < 4; ++i) {
            int fo = lane * 16 + i * 4;
            cp_async16(&xinA[c][fo], inA + c * CHUNK * DIN + fo);
            cp_async16(&xinB[c][fo], inB + c * CHUNK * DIN + fo);
        }
        cp_async_commit();
    }

    for (int c = 0; c < NCHUNK; ++c) {
        cp_async_wait1();
        __syncwarp();
        const int buf = c & 1;

#pragma unroll 2
        for (int tt = 0; tt < CHUNK; ++tt) {
            const int t = c * CHUNK + tt;

            const float4 xaA = *(const float4*)&xinA[buf][tt * DIN];
            const float4 xbA = *(const float4*)&xinA[buf][tt * DIN + 4];
            const float4 xaB = *(const float4*)&xinB[buf][tt * DIN];
            const float4 xbB = *(const float4*)&xinB[buf][tt * DIN + 4];

            // Input projections (off the recurrence chain), 2-acc trees.
            float qA0 = fmaf(win0[0], xaA.x, b0), qA1 = win0[1] * xaA.y;
            qA0 = fmaf(win0[2], xaA.z, qA0); qA1 = fmaf(win0[3], xaA.w, qA1);
            qA0 = fmaf(win0[4], xbA.x, qA0); qA1 = fmaf(win0[5], xbA.y, qA1);
            qA0 = fmaf(win0[6], xbA.z, qA0); qA1 = fmaf(win0[7], xbA.w, qA1);
            const float xpA0 = qA0 + qA1;

            float rA0 = fmaf(win1[0], xaA.x, b1), rA1 = win1[1] * xaA.y;
            rA0 = fmaf(win1[2], xaA.z, rA0); rA1 = fmaf(win1[3], xaA.w, rA1);
            rA0 = fmaf(win1[4], xbA.x, rA0); rA1 = fmaf(win1[5], xbA.y, rA1);
            rA0 = fmaf(win1[6], xbA.z, rA0); rA1 = fmaf(win1[7], xbA.w, rA1);
            const float xpA1 = rA0 + rA1;

            float qB0 = fmaf(win0[0], xaB.x, b0), qB1 = win0[1] * xaB.y;
            qB0 = fmaf(win0[2], xaB.z, qB0); qB1 = fmaf(win0[3], xaB.w, qB1);
            qB0 = fmaf(win0[4], xbB.x, qB0); qB1 = fmaf(win0[5], xbB.y, qB1);
            qB0 = fmaf(win0[6], xbB.z, qB0); qB1 = fmaf(win0[7], xbB.w, qB1);
            const float xpB0 = qB0 + qB1;

            float rB0 = fmaf(win1[0], xaB.x, b1), rB1 = win1[1] * xaB.y;
            rB0 = fmaf(win1[2], xaB.z, rB0); rB1 = fmaf(win1[3], xaB.w, rB1);
            rB0 = fmaf(win1[4], xbB.x, rB0); rB1 = fmaf(win1[5], xbB.y, rB1);
            rB0 = fmaf(win1[6], xbB.z, rB0); rB1 = fmaf(win1[7], xbB.w, rB1);
            const float xpB1 = rB0 + rB1;

            // Overflow path: publish previous state to SMEM (warp-uniform,
            // normally skipped entirely).
            if (nover) {
                shA[u0] = nA0; shA[u1] = nA1;
                shB[u0] = nB0; shB[u1] = nB1;
                __syncwarp();
            }

            // Recurrent gather: 4 shuffles per (column, slot) list.
            float a0[4] = {xpA0, 0.0f, 0.0f, 0.0f};
            float a1[4] = {xpA1, 0.0f, 0.0f, 0.0f};
            float e0[4] = {xpB0, 0.0f, 0.0f, 0.0f};
            float e1[4] = {xpB1, 0.0f, 0.0f, 0.0f};
#pragma unroll
            for (int k = 0; k < CAP; ++k) {
                const float gA0 = __shfl_sync(FULLMASK, nA0, s00[k]);
                const float gB0 = __shfl_sync(FULLMASK, nB0, s00[k]);
                a0[k] = fmaf(v00[k], gA0, a0[k]);
                e0[k] = fmaf(v00[k], gB0, e0[k]);
            }
#pragma unroll
            for (int k = 0; k < CAP; ++k) {
                const float gA1 = __shfl_sync(FULLMASK, nA1, s01[k]);
                const float gB1 = __shfl_sync(FULLMASK, nB1, s01[k]);
                a0[k] = fmaf(v01[k], gA1, a0[k]);
                e0[k] = fmaf(v01[k], gB1, e0[k]);
            }
#pragma unroll
            for (int k = 0; k < CAP; ++k) {
                const float gA0 = __shfl_sync(FULLMASK, nA0, s10[k]);
                const float gB0 = __shfl_sync(FULLMASK, nB0, s10[k]);
                a1[k] = fmaf(v10[k], gA0, a1[k]);
                e1[k] = fmaf(v10[k], gB0, e1[k]);
            }
#pragma unroll
            for (int k = 0; k < CAP; ++k) {
                const float gA1 = __shfl_sync(FULLMASK, nA1, s11[k]);
                const float gB1 = __shfl_sync(FULLMASK, nB1, s11[k]);
                a1[k] = fmaf(v11[k], gA1, a1[k]);
                e1[k] = fmaf(v11[k], gB1, e1[k]);
            }
            float zA0 = (a0[0] + a0[1]) + (a0[2] + a0[3]);
            float zA1 = (a1[0] + a1[1]) + (a1[2] + a1[3]);
            float zB0 = (e0[0] + e0[1]) + (e0[2] + e0[3]);
            float zB1 = (e1[0] + e1[1]) + (e1[2] + e1[3]);

            if (nover) {
                for (int k = 0; k < nover; ++k) {
                    const int   dd = g_ovdst[k];
                    const int   ss = g_ovsrc[k];
                    const float vv = g_ovval[k];
                    const float ca = vv * shA[ss];
                    const float cb = vv * shB[ss];
                    if (dd == u0) { zA0 += ca; zB0 += cb; }
                    if (dd == u1) { zA1 += ca; zB1 += cb; }
                }
                __syncwarp();
            }

            nA0 = fast_tanh(zA0);
            nA1 = fast_tanh(zA1);
            nB0 = fast_tanh(zB0);
            nB1 = fast_tanh(zB1);

            // Output (fire-and-forget).
            outA[(size_t)t * UNITS + u0] = nA0;
            outA[(size_t)t * UNITS + u1] = nA1;
            outB[(size_t)t * UNITS + u0] = nB0;
            outB[(size_t)t * UNITS + u1] = nB1;
        }

        // Prefetch chunk c+2 into the buffer just consumed.
        if (c + 2 < NCHUNK) {
#pragma unroll
            for (int i = 0; i < 4; ++i) {
                int fo = lane * 16 + i * 4;
                cp_async16(&xinA[buf][fo], inA + (c + 2) * CHUNK * DIN + fo);
                cp_async16(&xinB[buf][fo], inB + (c + 2) * CHUNK * DIN + fo);
            }
        }
        cp_async_commit();
    }
}

extern "C" void kernel_launch(void* const* d_in, const int* in_sizes, int n_in,
                              void* d_out, int out_size) {
    const float* inputs = (const float*)d_in[0];   // [256, 4096, 8]
    const float* W_in   = (const float*)d_in[1];   // [8, 64]
    const float* bias   = (const float*)d_in[2];   // [64]
    const float* W_rec  = (const float*)d_in[3];   // [64, 64]
    float* out = (float*)d_out;                    // [256, 4096, 64]

    esn_prep_kernel<<<1, UNITS>>>(W_rec);
    esn_main_kernel<<<BATCH / 2, 32>>>(inputs, W_in, bias, out);
}

// round 6
// speedup vs baseline: 2.0439x; 2.0439x over previous
#include <cuda_runtime.h>
#include <cuda_bf16.h>
#include <cstdint>

// ESN reservoir: B=256, T=4096, D=8, U=64, leaky=1.0
// state_t = tanh(x_proj_t + state_{t-1} @ W_rec), W_rec ~64 nnz total.
//
// State in registers, 2 units/lane (slot 0 / slot 1). Prep kernel greedily
// assigns units to register slots so each column's sources split evenly
// across slots, records the actual max per-(column,slot) count g_ncap, and
// the main kernel dispatches (warp-uniform) into a template-specialized
// time loop with exactly that many shuffles per list. Expected g_ncap = 2
// -> 8 shuffles/step. Exact SMEM overflow fallback for pathological draws.

#define BATCH  256
#define TLEN   4096
#define DIN    8
#define UNITS  64
#define CAPMAX 4
#define DEGCAP 12
#define CHUNK  64
#define NCHUNK (TLEN / CHUNK)
#define FULLMASK 0xffffffffu

__device__ int   g_unitOf[2][32];             // [slot][lane] -> unit id
__device__ int   g_lsrc[UNITS][2][CAPMAX];    // [col][slot][k] -> source lane
__device__ float g_lval[UNITS][2][CAPMAX];
__device__ int   g_ncap;                      // max used slots (1..CAPMAX)
__device__ int   g_nover;
__device__ int   g_ovdst[256];
__device__ int   g_ovsrc[256];
__device__ float g_ovval[256];

__global__ void esn_prep_kernel(const float* __restrict__ W) {
    __shared__ int   s_cols[UNITS][DEGCAP];
    __shared__ int   s_deg[UNITS];
    __shared__ int   s_slot[UNITS], s_lane[UNITS];
    __shared__ int   s_ovn[UNITS];
    __shared__ int   s_cnt[UNITS][2];
    __shared__ int   s_ovsrc[UNITS][8];
    __shared__ float s_ovval[UNITS][8];

    const int tid = threadIdx.x;

    // Phase A: per-source-row nonzero column lists.
    if (tid < UNITS) {
        int d = 0;
        for (int c = 0; c < UNITS; ++c) {
            float v = W[tid * UNITS + c];
            if (v != 0.0f && d < DEGCAP) { s_cols[tid][d] = c; ++d; }
        }
        s_deg[tid] = d;
    }
    __syncthreads();

    // Phase B (serial, deterministic): greedy slot assignment balancing each
    // column's source count across the two register slots.
    if (tid == 0) {
        int load[UNITS][2];
        for (int c = 0; c < UNITS; ++c) { load[c][0] = 0; load[c][1] = 0; }
        int cnt0 = 0, cnt1 = 0;
        for (int j = 0; j < UNITS; ++j) {
            int c0 = 0, c1 = 0;
            for (int k = 0; k < s_deg[j]; ++k) {
                int c = s_cols[j][k];
                if (load[c][0] > c0) c0 = load[c][0];
                if (load[c][1] > c1) c1 = load[c][1];
            }
            int s;
            if (cnt0 >= 32) s = 1;
            else if (cnt1 >= 32) s = 0;
            else if (c0 != c1) s = (c0 < c1) ? 0 : 1;
            else s = (cnt0 <= cnt1) ? 0 : 1;
            s_slot[j] = s;
            s_lane[j] = (s == 0) ? cnt0++ : cnt1++;
            for (int k = 0; k < s_deg[j]; ++k) load[s_cols[j][k]][s]++;
        }
    }
    __syncthreads();

    // Phase C: per-column shuffle lists + per-column overflow + counts.
    if (tid < UNITS) {
        const int c = tid;
        int n0 = 0, n1 = 0, ovn = 0;
        for (int j = 0; j < UNITS; ++j) {
            float v = W[j * UNITS + c];
            if (v == 0.0f) continue;
            int s = s_slot[j];
            if (s == 0 && n0 < CAPMAX)      { g_lsrc[c][0][n0] = s_lane[j]; g_lval[c][0][n0] = v; ++n0; }
            else if (s == 1 && n1 < CAPMAX) { g_lsrc[c][1][n1] = s_lane[j]; g_lval[c][1][n1] = v; ++n1; }
            else if (ovn < 8)               { s_ovsrc[c][ovn] = j; s_ovval[c][ovn] = v; ++ovn; }
        }
        for (int k = n0; k < CAPMAX; ++k) { g_lsrc[c][0][k] = 0; g_lval[c][0][k] = 0.0f; }
        for (int k = n1; k < CAPMAX; ++k) { g_lsrc[c][1][k] = 0; g_lval[c][1][k] = 0.0f; }
        s_cnt[c][0] = n0; s_cnt[c][1] = n1;
        s_ovn[c] = ovn;
        g_unitOf[s_slot[tid]][s_lane[tid]] = tid;
    }
    __syncthreads();

    // Phase D (serial): compact overflow + max cap.
    if (tid == 0) {
        int n = 0, mx = 1;
        for (int c = 0; c < UNITS; ++c) {
            if (s_cnt[c][0] > mx) mx = s_cnt[c][0];
            if (s_cnt[c][1] > mx) mx = s_cnt[c][1];
            for (int k = 0; k < s_ovn[c]; ++k) {
                g_ovdst[n] = c; g_ovsrc[n] = s_ovsrc[c][k]; g_ovval[n] = s_ovval[c][k]; ++n;
            }
        }
        g_nover = n;
        g_ncap  = mx;
    }
}

// tanh(x) = (e-1)*rcp(e+1), e = exp(2x). Rel err ~1e-6.
__device__ __forceinline__ float fast_tanh(float x) {
    float e;
    asm("ex2.approx.f32 %0, %1;" : "=f"(e) : "f"(x * 2.8853900817779268f));
    float r;
    asm("rcp.approx.f32 %0, %1;" : "=f"(r) : "f"(e + 1.0f));
    return (e - 1.0f) * r;
}

__device__ __forceinline__ void cp_async16(void* smem_dst, const void* gmem_src) {
    uint32_t s = (uint32_t)__cvta_generic_to_shared(smem_dst);
    asm volatile("cp.async.cg.shared.global [%0], [%1], 16;\n" :: "r"(s), "l"(gmem_src));
}
__device__ __forceinline__ void cp_async_commit() {
    asm volatile("cp.async.commit_group;\n");
}
__device__ __forceinline__ void cp_async_wait1() {
    asm volatile("cp.async.wait_group 1;\n");
}

template <int NC>
__device__ __forceinline__ void time_loop(
    const int lane, const int u0, const int u1,
    const float (&win0)[DIN], const float (&win1)[DIN],
    const float b0, const float b1,
    const float* __restrict__ inp_b, float* __restrict__ out_b,
    float (&xin)[2][CHUNK * DIN], float (&sh)[UNITS],
    const int nover)
{
    // Shuffle lists (registers, length NC).
    int   s00[NC], s01[NC], s10[NC], s11[NC];
    float v00[NC], v01[NC], v10[NC], v11[NC];
#pragma unroll
    for (int k = 0; k < NC; ++k) {
        s00[k] = g_lsrc[u0][0][k];  v00[k] = g_lval[u0][0][k];
        s01[k] = g_lsrc[u0][1][k];  v01[k] = g_lval[u0][1][k];
        s10[k] = g_lsrc[u1][0][k];  v10[k] = g_lval[u1][0][k];
        s11[k] = g_lsrc[u1][1][k];  v11[k] = g_lval[u1][1][k];
    }

    float n0 = 0.0f;   // state of unit u0
    float n1 = 0.0f;   // state of unit u1

    // Prefetch input chunks 0 and 1 (2048B each; lane copies 4x16B).
#pragma unroll
    for (int c = 0; c < 2; ++c) {
        const float* src = inp_b + c * CHUNK * DIN;
#pragma unroll
        for (int i = 0; i < 4; ++i) {
            int fo = lane * 16 + i * 4;
            cp_async16(&xin[c][fo], src + fo);
        }
        cp_async_commit();
    }

    for (int c = 0; c < NCHUNK; ++c) {
        cp_async_wait1();
        __syncwarp();
        const int buf = c & 1;

#pragma unroll 4
        for (int tt = 0; tt < CHUNK; ++tt) {
            const int t = c * CHUNK + tt;

            const float4 xa = *(const float4*)&xin[buf][tt * DIN];
            const float4 xb = *(const float4*)&xin[buf][tt * DIN + 4];

            // Input projection (off-chain), 2-acc trees.
            float q0 = fmaf(win0[0], xa.x, b0), q1 = win0[1] * xa.y;
            q0 = fmaf(win0[2], xa.z, q0); q1 = fmaf(win0[3], xa.w, q1);
            q0 = fmaf(win0[4], xb.x, q0); q1 = fmaf(win0[5], xb.y, q1);
            q0 = fmaf(win0[6], xb.z, q0); q1 = fmaf(win0[7], xb.w, q1);
            const float xp0 = q0 + q1;

            float r0 = fmaf(win1[0], xa.x, b1), r1 = win1[1] * xa.y;
            r0 = fmaf(win1[2], xa.z, r0); r1 = fmaf(win1[3], xa.w, r1);
            r0 = fmaf(win1[4], xb.x, r0); r1 = fmaf(win1[5], xb.y, r1);
            r0 = fmaf(win1[6], xb.z, r0); r1 = fmaf(win1[7], xb.w, r1);
            const float xp1 = r0 + r1;

            // Overflow publish (warp-uniform; normally skipped).
            if (nover) {
                sh[u0] = n0; sh[u1] = n1;
                __syncwarp();
            }

            // Recurrent gather: NC shuffles per (column, slot) list.
            float a0 = xp0, a0b = 0.0f;
            float a1 = xp1, a1b = 0.0f;
#pragma unroll
            for (int k = 0; k < NC; ++k) {
                a0  = fmaf(v00[k], __shfl_sync(FULLMASK, n0, s00[k]), a0);
                a0b = fmaf(v01[k], __shfl_sync(FULLMASK, n1, s01[k]), a0b);
                a1  = fmaf(v10[k], __shfl_sync(FULLMASK, n0, s10[k]), a1);
                a1b = fmaf(v11[k], __shfl_sync(FULLMASK, n1, s11[k]), a1b);
            }
            float z0 = a0 + a0b;
            float z1 = a1 + a1b;

            if (nover) {
                for (int k = 0; k < nover; ++k) {
                    const float ctr = g_ovval[k] * sh[g_ovsrc[k]];
                    const int dd = g_ovdst[k];
                    if (dd == u0) z0 += ctr;
                    if (dd == u1) z1 += ctr;
                }
                __syncwarp();
            }

            n0 = fast_tanh(z0);
            n1 = fast_tanh(z1);

            out_b[(size_t)t * UNITS + u0] = n0;
            out_b[(size_t)t * UNITS + u1] = n1;
        }

        // Prefetch chunk c+2 into the buffer just consumed.
        if (c + 2 < NCHUNK) {
            const float* src = inp_b + (c + 2) * CHUNK * DIN;
#pragma unroll
            for (int i = 0; i < 4; ++i) {
                int fo = lane * 16 + i * 4;
                cp_async16(&xin[buf][fo], src + fo);
            }
        }
        cp_async_commit();
    }
}

__global__ void __launch_bounds__(32)
esn_main_kernel(const float* __restrict__ inputs,
                const float* __restrict__ W_in,
                const float* __restrict__ bias,
                float* __restrict__ out) {
    const int lane = threadIdx.x;
    const int b    = blockIdx.x;

    __shared__ float xin[2][CHUNK * DIN];
    __shared__ float sh[UNITS];

    const int u0 = g_unitOf[0][lane];
    const int u1 = g_unitOf[1][lane];

    float win0[DIN], win1[DIN];
#pragma unroll
    for (int d = 0; d < DIN; ++d) {
        win0[d] = W_in[d * UNITS + u0];
        win1[d] = W_in[d * UNITS + u1];
    }
    const float b0 = bias[u0];
    const float b1 = bias[u1];

    const float* inp_b = inputs + (size_t)b * TLEN * DIN;
    float*       out_b = out    + (size_t)b * TLEN * UNITS;

    const int nover = g_nover;
    const int ncap  = g_ncap;      // warp-uniform dispatch

    if (ncap <= 1)
        time_loop<1>(lane, u0, u1, win0, win1, b0, b1, inp_b, out_b, xin, sh, nover);
    else if (ncap == 2)
        time_loop<2>(lane, u0, u1, win0, win1, b0, b1, inp_b, out_b, xin, sh, nover);
    else if (ncap == 3)
        time_loop<3>(lane, u0, u1, win0, win1, b0, b1, inp_b, out_b, xin, sh, nover);
    else
        time_loop<4>(lane, u0, u1, win0, win1, b0, b1, inp_b, out_b, xin, sh, nover);
}

extern "C" void kernel_launch(void* const* d_in, const int* in_sizes, int n_in,
                              void* d_out, int out_size) {
    const float* inputs = (const float*)d_in[0];   // [256, 4096, 8]
    const float* W_in   = (const float*)d_in[1];   // [8, 64]
    const float* bias   = (const float*)d_in[2];   // [64]
    const float* W_rec  = (const float*)d_in[3];   // [64, 64]
    float* out = (float*)d_out;                    // [256, 4096, 64]

    esn_prep_kernel<<<1, UNITS>>>(W_rec);
    esn_main_kernel<<<BATCH, 32>>>(inputs, W_in, bias, out);
}